// round 4
// baseline (speedup 1.0000x reference)
#include <cuda_runtime.h>
#include <cstdint>

typedef unsigned long long u64;

// ---------- packed dual-fp32 helpers (f32x2, PTX-only) ----------
__device__ __forceinline__ u64 pack2(float x, float y) {
    u64 r; asm("mov.b64 %0, {%1, %2};" : "=l"(r) : "f"(x), "f"(y)); return r;
}
__device__ __forceinline__ void unpack2(u64 v, float& x, float& y) {
    asm("mov.b64 {%0, %1}, %2;" : "=f"(x), "=f"(y) : "l"(v));
}
__device__ __forceinline__ u64 ffma2(u64 a, u64 b, u64 c) {
    u64 d; asm("fma.rn.f32x2 %0, %1, %2, %3;" : "=l"(d) : "l"(a), "l"(b), "l"(c)); return d;
}

// ---------- accurate fast transcendentals (MUFU EX2 + RCP, ~1e-6 rel) ----------
__device__ __forceinline__ float sigmoid_f(float x) {
    float e = __expf(-x);
    return __fdividef(1.0f, 1.0f + e);
}
__device__ __forceinline__ float tanh_f(float x) {
    float e = __expf(-2.0f * x);
    return __fdividef(1.0f - e, 1.0f + e);
}

// Per-thread loop-invariant constants: all weights this thread ever touches.
// Column set for thread d: {d, 16+d, 32+d, 48+d}; k packed in pairs (2j, 2j+1).
struct NodeConsts {
    u64 wi[12], wf[12], wc[12], wo[12];   // 48 f32x2 pairs = 96 regs
    u64 bi2, bf2, bc2, bo2;               // (fused bias, 0) accumulator seeds
    float wp0, wp1, wp2, wld, bl;
};

__device__ __forceinline__ void load_node(const float* __restrict__ x,
                                          const float* __restrict__ h,
                                          const float* __restrict__ c,
                                          long long n, int d,
                                          u64 (&in2)[12], float& cv)
{
    // x[n][0..7]: 2x LDG.128; h[n][0..15]: 4x LDG.128. k-pairs land directly
    // in u64 lanes (little-endian: .x = (k, k+1)) -> zero packing ops.
    const ulonglong2* xv = reinterpret_cast<const ulonglong2*>(x + n * 8);
    ulonglong2 a = xv[0], b = xv[1];
    in2[0] = a.x; in2[1] = a.y; in2[2] = b.x; in2[3] = b.y;
    const ulonglong2* hv = reinterpret_cast<const ulonglong2*>(h + n * 16);
#pragma unroll
    for (int q = 0; q < 4; ++q) {
        ulonglong2 v = hv[q];
        in2[4 + 2 * q] = v.x;
        in2[5 + 2 * q] = v.y;
    }
    cv = c[n * 16 + d];
}

__device__ __forceinline__ void compute_node(const NodeConsts& K,
                                             const u64 (&in2)[12], float cv,
                                             long long n, int d, bool valid,
                                             float* __restrict__ out,
                                             float* __restrict__ h_new,
                                             float* __restrict__ c_new)
{
    // 4 independent f32x2 accumulation chains (i, f, c, o gates).
    u64 ai = ffma2(in2[0], K.wi[0], K.bi2);
    u64 af = ffma2(in2[0], K.wf[0], K.bf2);
    u64 ac = ffma2(in2[0], K.wc[0], K.bc2);
    u64 ao = ffma2(in2[0], K.wo[0], K.bo2);
#pragma unroll
    for (int j = 1; j < 12; ++j) {
        ai = ffma2(in2[j], K.wi[j], ai);
        af = ffma2(in2[j], K.wf[j], af);
        ac = ffma2(in2[j], K.wc[j], ac);
        ao = ffma2(in2[j], K.wo[j], ao);
    }
    float g0, g1, gi, gf, gc, go;
    unpack2(ai, g0, g1); gi = g0 + g1;
    unpack2(af, g0, g1); gf = g0 + g1;
    unpack2(ac, g0, g1); gc = g0 + g1;
    unpack2(ao, g0, g1); go = g0 + g1;

    float iv = sigmoid_f(fmaf(K.wp0, cv, gi));
    float fv = sigmoid_f(fmaf(K.wp1, cv, gf));
    float tv = tanh_f(gc);
    float cn = fmaf(fv, cv, iv * tv);
    float ov = sigmoid_f(fmaf(K.wp2, cn, go));
    float hn = ov * tanh_f(cn);

    // out[n] = b_lin + sum_d relu(hn[d]) * W_lin[d] over the 16-lane group.
    float r = fmaxf(hn, 0.0f) * K.wld;
    r += __shfl_xor_sync(0xffffffffu, r, 1);
    r += __shfl_xor_sync(0xffffffffu, r, 2);
    r += __shfl_xor_sync(0xffffffffu, r, 4);
    r += __shfl_xor_sync(0xffffffffu, r, 8);

    if (valid) {
        c_new[n * 16 + d] = cn;
        h_new[n * 16 + d] = hn;
        if (d == 0) out[n] = r + K.bl;
    }
}

__global__ __launch_bounds__(128, 2)
void gconvlstm_kernel(const float* __restrict__ x,
                      const float* __restrict__ h,
                      const float* __restrict__ c,
                      const float* __restrict__ Wx, const float* __restrict__ bx,
                      const float* __restrict__ Wh, const float* __restrict__ bh,
                      const float* __restrict__ w_peep,
                      const float* __restrict__ b_gates,
                      const float* __restrict__ W_lin,
                      const float* __restrict__ b_lin,
                      float* __restrict__ out,
                      float* __restrict__ h_new,
                      float* __restrict__ c_new,
                      int N)
{
    const int lane = threadIdx.x & 31;
    const int s = lane >> 4;        // node slot within warp (0/1)
    const int d = lane & 15;        // feature index

    // ---- one-time weight staging into registers (amortized ~850 nodes/thread) ----
    NodeConsts K;
#pragma unroll
    for (int j = 0; j < 12; ++j) {
        const int k0 = 2 * j, k1 = k0 + 1;
        const float* r0 = (k0 < 8) ? (Wx + k0 * 64) : (Wh + (k0 - 8) * 64);
        const float* r1 = (k1 < 8) ? (Wx + k1 * 64) : (Wh + (k1 - 8) * 64);
        K.wi[j] = pack2(r0[d],      r1[d]);
        K.wf[j] = pack2(r0[16 + d], r1[16 + d]);
        K.wc[j] = pack2(r0[32 + d], r1[32 + d]);
        K.wo[j] = pack2(r0[48 + d], r1[48 + d]);
    }
    K.bi2 = pack2(bx[d]      + bh[d]      + b_gates[d],      0.0f);
    K.bf2 = pack2(bx[16 + d] + bh[16 + d] + b_gates[16 + d], 0.0f);
    K.bc2 = pack2(bx[32 + d] + bh[32 + d] + b_gates[32 + d], 0.0f);
    K.bo2 = pack2(bx[48 + d] + bh[48 + d] + b_gates[48 + d], 0.0f);
    K.wp0 = w_peep[d]; K.wp1 = w_peep[16 + d]; K.wp2 = w_peep[32 + d];
    K.wld = W_lin[d];  K.bl  = b_lin[0];

    // ---- persistent grid-stride over node pairs, ping-pong load pipeline ----
    const long long npairs = ((long long)N + 1) >> 1;
    const long long stride = (long long)gridDim.x * (blockDim.x >> 5);
    long long p = (long long)blockIdx.x * (blockDim.x >> 5) + (threadIdx.x >> 5);
    if (p >= npairs) return;

    u64 A[12], B[12];
    float cA = 0.0f, cB = 0.0f;
    long long nA = 2 * p + s;
    bool vA = nA < N; if (!vA) nA = N - 1;
    load_node(x, h, c, nA, d, A, cA);

    long long nB = 0; bool vB = false;

    while (true) {
        // prefetch B @ p+stride, compute A @ p
        long long p1 = p + stride;
        if (p1 < npairs) {
            nB = 2 * p1 + s; vB = nB < N; if (!vB) nB = N - 1;
            load_node(x, h, c, nB, d, B, cB);
        }
        compute_node(K, A, cA, nA, d, vA, out, h_new, c_new);
        if (p1 >= npairs) break;

        // prefetch A @ p+2*stride, compute B @ p+stride
        p = p1 + stride;
        if (p < npairs) {
            nA = 2 * p + s; vA = nA < N; if (!vA) nA = N - 1;
            load_node(x, h, c, nA, d, A, cA);
        }
        compute_node(K, B, cB, nB, d, vB, out, h_new, c_new);
        if (p >= npairs) break;
    }
}

extern "C" void kernel_launch(void* const* d_in, const int* in_sizes, int n_in,
                              void* d_out, int out_size) {
    // metadata order: x, edge_index(unused), edge_attr(unused), h, c,
    //                 Wx, bx, Wh, bh, w_peep, b_gates, W_lin, b_lin
    const float* x  = (const float*)d_in[0];
    const float* h  = (const float*)d_in[3];
    const float* c  = (const float*)d_in[4];
    const float* Wx = (const float*)d_in[5];
    const float* bx = (const float*)d_in[6];
    const float* Wh = (const float*)d_in[7];
    const float* bh = (const float*)d_in[8];
    const float* wp = (const float*)d_in[9];
    const float* bg = (const float*)d_in[10];
    const float* wl = (const float*)d_in[11];
    const float* bl = (const float*)d_in[12];

    const int N = in_sizes[0] / 8;   // x is (N, 8)

    // outputs concatenated in reference return order: out[N], h_new[N*16], c_new[N*16]
    float* out = (float*)d_out;
    float* hn  = out + (size_t)N;
    float* cn  = hn + (size_t)N * 16;

    const int threads = 128;
    const int blocks  = 296;   // 2 resident blocks x 148 SMs, grid-stride persistent
    gconvlstm_kernel<<<blocks, threads>>>(x, h, c, Wx, bx, Wh, bh, wp, bg, wl, bl,
                                          out, hn, cn, N);
}

// round 5
// speedup vs baseline: 1.7503x; 1.7503x over previous
#include <cuda_runtime.h>
#include <cstdint>

typedef unsigned long long u64;

// ---------- packed dual-fp32 helpers (f32x2, PTX-only) ----------
__device__ __forceinline__ u64 pack2(float x, float y) {
    u64 r; asm("mov.b64 %0, {%1, %2};" : "=l"(r) : "f"(x), "f"(y)); return r;
}
__device__ __forceinline__ void unpack2(u64 v, float& x, float& y) {
    asm("mov.b64 {%0, %1}, %2;" : "=f"(x), "=f"(y) : "l"(v));
}
__device__ __forceinline__ u64 ffma2(u64 a, u64 b, u64 c) {
    u64 d; asm("fma.rn.f32x2 %0, %1, %2, %3;" : "=l"(d) : "l"(a), "l"(b), "l"(c)); return d;
}

// ---------- accurate fast transcendentals (MUFU EX2 + RCP, ~1e-6 rel) ----------
__device__ __forceinline__ float sigmoid_f(float x) {
    float e = __expf(-x);
    return __fdividef(1.0f, 1.0f + e);
}
__device__ __forceinline__ float tanh_f(float x) {
    float e = __expf(-2.0f * x);
    return __fdividef(1.0f - e, 1.0f + e);
}

// ---------- cp.async helpers ----------
__device__ __forceinline__ void cp16(uint32_t dst_smem, const void* src) {
    asm volatile("cp.async.cg.shared.global [%0], [%1], 16;" :: "r"(dst_smem), "l"(src));
}
__device__ __forceinline__ void cp_commit()  { asm volatile("cp.async.commit_group;"); }
__device__ __forceinline__ void cp_wait1()   { asm volatile("cp.async.wait_group 1;"); }
__device__ __forceinline__ void cp_wait0()   { asm volatile("cp.async.wait_group 0;"); }

// Per-thread loop-invariant weights: column set {d, 16+d, 32+d, 48+d},
// k packed in pairs so inputs are consumed directly as loaded u64 lanes.
struct NodeConsts {
    u64 wi[12], wf[12], wc[12], wo[12];   // 48 f32x2 pairs
    u64 bi2, bf2, bc2, bo2;               // (fused bias, 0) accumulator seeds
    float wp0, wp1, wp2, wld, bl;
};

// Smem ring: per warp, 3 stages, 2 nodes, 40 floats (x:8, h:16, c:16) = 160B/node.
#define WARPS_PER_BLOCK 4
#define STAGES 3
#define NODE_F 40   // floats per node slot

// Issue cp.async for one stage: lanes 0-9 copy node A's 10x16B chunks, 16-25 node B's.
__device__ __forceinline__ void issue_stage(uint32_t slot_smem,  // base of [2][40] floats
                                            int lane, long long p, long long npairs, int N,
                                            const float* __restrict__ x,
                                            const float* __restrict__ h,
                                            const float* __restrict__ c)
{
    if (p >= npairs) p = npairs - 1;
    const int s = lane >> 4;
    const int j = lane & 15;
    long long n = 2 * p + s;
    if (n >= N) n = N - 1;
    if (j < 10) {
        const float* src;
        if (j < 2)      src = x + n * 8  + j * 4;
        else if (j < 6) src = h + n * 16 + (j - 2) * 4;
        else            src = c + n * 16 + (j - 6) * 4;
        cp16(slot_smem + (uint32_t)(s * NODE_F * 4 + j * 16), src);
    }
}

__global__ __launch_bounds__(128, 3)
void gconvlstm_kernel(const float* __restrict__ x,
                      const float* __restrict__ h,
                      const float* __restrict__ c,
                      const float* __restrict__ Wx, const float* __restrict__ bx,
                      const float* __restrict__ Wh, const float* __restrict__ bh,
                      const float* __restrict__ w_peep,
                      const float* __restrict__ b_gates,
                      const float* __restrict__ W_lin,
                      const float* __restrict__ b_lin,
                      float* __restrict__ out,
                      float* __restrict__ h_new,
                      float* __restrict__ c_new,
                      int N)
{
    __shared__ __align__(16) float ring[WARPS_PER_BLOCK][STAGES][2][NODE_F];

    const int lane = threadIdx.x & 31;
    const int warp = threadIdx.x >> 5;
    const int s = lane >> 4;        // node slot within warp (0/1)
    const int d = lane & 15;        // feature index

    // ---- one-time weight staging into registers ----
    NodeConsts K;
#pragma unroll
    for (int j = 0; j < 12; ++j) {
        const int k0 = 2 * j, k1 = k0 + 1;
        const float* r0 = (k0 < 8) ? (Wx + k0 * 64) : (Wh + (k0 - 8) * 64);
        const float* r1 = (k1 < 8) ? (Wx + k1 * 64) : (Wh + (k1 - 8) * 64);
        K.wi[j] = pack2(r0[d],      r1[d]);
        K.wf[j] = pack2(r0[16 + d], r1[16 + d]);
        K.wc[j] = pack2(r0[32 + d], r1[32 + d]);
        K.wo[j] = pack2(r0[48 + d], r1[48 + d]);
    }
    K.bi2 = pack2(bx[d]      + bh[d]      + b_gates[d],      0.0f);
    K.bf2 = pack2(bx[16 + d] + bh[16 + d] + b_gates[16 + d], 0.0f);
    K.bc2 = pack2(bx[32 + d] + bh[32 + d] + b_gates[32 + d], 0.0f);
    K.bo2 = pack2(bx[48 + d] + bh[48 + d] + b_gates[48 + d], 0.0f);
    K.wp0 = w_peep[d]; K.wp1 = w_peep[16 + d]; K.wp2 = w_peep[32 + d];
    K.wld = W_lin[d];  K.bl  = b_lin[0];

    const long long npairs = ((long long)N + 1) >> 1;
    const long long stride = (long long)gridDim.x * WARPS_PER_BLOCK;
    const long long p0 = (long long)blockIdx.x * WARPS_PER_BLOCK + warp;
    if (p0 >= npairs) return;

    uint32_t ring_smem = (uint32_t)__cvta_generic_to_shared(&ring[warp][0][0][0]);
    const uint32_t stage_bytes = 2 * NODE_F * 4;   // 320

    // ---- prologue: fill stages 0 and 1 ----
    issue_stage(ring_smem + 0 * stage_bytes, lane, p0,          npairs, N, x, h, c);
    cp_commit();
    issue_stage(ring_smem + 1 * stage_bytes, lane, p0 + stride, npairs, N, x, h, c);
    cp_commit();

    int st = 0;
    for (long long p = p0; p < npairs; p += stride) {
        cp_wait1();
        __syncwarp();

        // ---- consume stage st ----
        const float* nb = &ring[warp][st][s][0];
        u64 in2[12];
        {
            const ulonglong2* v = reinterpret_cast<const ulonglong2*>(nb);
#pragma unroll
            for (int q = 0; q < 6; ++q) {          // x: v[0..1], h: v[2..5]
                ulonglong2 t = v[q];
                in2[2 * q]     = t.x;
                in2[2 * q + 1] = t.y;
            }
        }
        const float cv = nb[24 + d];

        // ---- prefetch stage st+2 (pair p + 2*stride) ----
        issue_stage(ring_smem + (uint32_t)(((st + 2) % STAGES) * stage_bytes),
                    lane, p + 2 * stride, npairs, N, x, h, c);
        cp_commit();

        // ---- 4 independent f32x2 gate chains ----
        u64 ai = ffma2(in2[0], K.wi[0], K.bi2);
        u64 af = ffma2(in2[0], K.wf[0], K.bf2);
        u64 ac = ffma2(in2[0], K.wc[0], K.bc2);
        u64 ao = ffma2(in2[0], K.wo[0], K.bo2);
#pragma unroll
        for (int j = 1; j < 12; ++j) {
            ai = ffma2(in2[j], K.wi[j], ai);
            af = ffma2(in2[j], K.wf[j], af);
            ac = ffma2(in2[j], K.wc[j], ac);
            ao = ffma2(in2[j], K.wo[j], ao);
        }
        float g0, g1, gi, gf, gc, go;
        unpack2(ai, g0, g1); gi = g0 + g1;
        unpack2(af, g0, g1); gf = g0 + g1;
        unpack2(ac, g0, g1); gc = g0 + g1;
        unpack2(ao, g0, g1); go = g0 + g1;

        const float iv = sigmoid_f(fmaf(K.wp0, cv, gi));
        const float fv = sigmoid_f(fmaf(K.wp1, cv, gf));
        const float tv = tanh_f(gc);
        const float cn = fmaf(fv, cv, iv * tv);
        const float ov = sigmoid_f(fmaf(K.wp2, cn, go));
        const float hn = ov * tanh_f(cn);

        // out[n] = b_lin + sum_d relu(hn)*W_lin[d], reduced within the 16-lane half.
        float r = fmaxf(hn, 0.0f) * K.wld;
        r += __shfl_xor_sync(0xffffffffu, r, 1);
        r += __shfl_xor_sync(0xffffffffu, r, 2);
        r += __shfl_xor_sync(0xffffffffu, r, 4);
        r += __shfl_xor_sync(0xffffffffu, r, 8);

        const long long n = 2 * p + s;
        if (n < N) {
            c_new[n * 16 + d] = cn;    // lanes 0-31 -> contiguous 128B
            h_new[n * 16 + d] = hn;
            if (d == 0) out[n] = r + K.bl;
        }

        __syncwarp();                  // slot st free only after all lanes consumed it
        st = (st + 1) % STAGES;
    }
    cp_wait0();
}

extern "C" void kernel_launch(void* const* d_in, const int* in_sizes, int n_in,
                              void* d_out, int out_size) {
    // metadata order: x, edge_index(unused), edge_attr(unused), h, c,
    //                 Wx, bx, Wh, bh, w_peep, b_gates, W_lin, b_lin
    const float* x  = (const float*)d_in[0];
    const float* h  = (const float*)d_in[3];
    const float* c  = (const float*)d_in[4];
    const float* Wx = (const float*)d_in[5];
    const float* bx = (const float*)d_in[6];
    const float* Wh = (const float*)d_in[7];
    const float* bh = (const float*)d_in[8];
    const float* wp = (const float*)d_in[9];
    const float* bg = (const float*)d_in[10];
    const float* wl = (const float*)d_in[11];
    const float* bl = (const float*)d_in[12];

    const int N = in_sizes[0] / 8;   // x is (N, 8)

    float* out = (float*)d_out;
    float* hn  = out + (size_t)N;
    float* cn  = hn + (size_t)N * 16;

    const int threads = 128;
    const int blocks  = 444;   // 3 resident blocks x 148 SMs, persistent grid-stride
    gconvlstm_kernel<<<blocks, threads>>>(x, h, c, Wx, bx, Wh, bh, wp, bg, wl, bl,
                                          out, hn, cn, N);
}

// round 6
// speedup vs baseline: 2.3488x; 1.3419x over previous
#include <cuda_runtime.h>
#include <cstdint>

typedef unsigned long long u64;

// ---------- packed dual-fp32 helpers (f32x2; falls back to 2xFFMA if unpacked) ----------
__device__ __forceinline__ u64 pack2(float x, float y) {
    u64 r; asm("mov.b64 %0, {%1, %2};" : "=l"(r) : "f"(x), "f"(y)); return r;
}
__device__ __forceinline__ void unpack2(u64 v, float& x, float& y) {
    asm("mov.b64 {%0, %1}, %2;" : "=f"(x), "=f"(y) : "l"(v));
}
__device__ __forceinline__ u64 ffma2(u64 a, u64 b, u64 c) {
    u64 d; asm("fma.rn.f32x2 %0, %1, %2, %3;" : "=l"(d) : "l"(a), "l"(b), "l"(c)); return d;
}

// ---------- accurate fast transcendentals (MUFU EX2 + RCP, ~1e-7 rel) ----------
__device__ __forceinline__ float sigmoid_f(float x) {
    float e = __expf(-x);
    return __fdividef(1.0f, 1.0f + e);
}
__device__ __forceinline__ float tanh_f(float x) {
    float e = __expf(-2.0f * x);
    return __fdividef(1.0f - e, 1.0f + e);
}

// ---------- cp.async helpers ----------
__device__ __forceinline__ void cp16(uint32_t dst_smem, const float* src) {
    asm volatile("cp.async.cg.shared.global [%0], [%1], 16;" :: "r"(dst_smem), "l"(src));
}
__device__ __forceinline__ void cp_commit() { asm volatile("cp.async.commit_group;"); }
__device__ __forceinline__ void cp_wait2()  { asm volatile("cp.async.wait_group 2;"); }
__device__ __forceinline__ void cp_wait0()  { asm volatile("cp.async.wait_group 0;"); }

// Per-thread loop-invariant weights: column set {d,16+d,32+d,48+d}, k in pairs.
struct NodeConsts {
    u64 wi[12], wf[12], wc[12], wo[12];
    u64 bi2, bf2, bc2, bo2;
    float wp0, wp1, wp2, wld, bl;
};

#define WPB    4            // warps per block
#define STAGES 4
#define GROUP  8            // nodes per warp-iteration (4 pairs)
// Stage float layout: x[8][8] @0, h[8][16] @64, c[8][16] @192 -> 320 floats
#define ST_X 0
#define ST_H 64
#define ST_C 192
#define ST_F 320
#define ST_BYTES (ST_F * 4)

// Fill one stage for node group starting at n0 (n0 pre-clamped, 32B/64B aligned rows).
__device__ __forceinline__ void issue_group(uint32_t sb, int lane, int n0,
                                            const float* __restrict__ x,
                                            const float* __restrict__ h,
                                            const float* __restrict__ c)
{
    const int l4 = lane * 4;
    cp16(sb + ST_H * 4 + lane * 16, h + n0 * 16 + l4);   // 8 nodes x 64B, coalesced
    cp16(sb + ST_C * 4 + lane * 16, c + n0 * 16 + l4);
    if (lane < 16)
        cp16(sb + ST_X * 4 + lane * 16, x + n0 * 8 + l4); // 8 nodes x 32B
}

__global__ __launch_bounds__(128, 3)
void gconvlstm_kernel(const float* __restrict__ x,
                      const float* __restrict__ h,
                      const float* __restrict__ c,
                      const float* __restrict__ Wx, const float* __restrict__ bx,
                      const float* __restrict__ Wh, const float* __restrict__ bh,
                      const float* __restrict__ w_peep,
                      const float* __restrict__ b_gates,
                      const float* __restrict__ W_lin,
                      const float* __restrict__ b_lin,
                      float* __restrict__ out,
                      float* __restrict__ h_new,
                      float* __restrict__ c_new,
                      int N)
{
    __shared__ __align__(16) float ring[WPB][STAGES][ST_F];

    const int lane = threadIdx.x & 31;
    const int warp = threadIdx.x >> 5;
    const int s = lane >> 4;      // node slot within pair
    const int d = lane & 15;      // feature index

    // ---- one-time weight staging into registers ----
    NodeConsts K;
#pragma unroll
    for (int j = 0; j < 12; ++j) {
        const int k0 = 2 * j, k1 = k0 + 1;
        const float* r0 = (k0 < 8) ? (Wx + k0 * 64) : (Wh + (k0 - 8) * 64);
        const float* r1 = (k1 < 8) ? (Wx + k1 * 64) : (Wh + (k1 - 8) * 64);
        K.wi[j] = pack2(r0[d],      r1[d]);
        K.wf[j] = pack2(r0[16 + d], r1[16 + d]);
        K.wc[j] = pack2(r0[32 + d], r1[32 + d]);
        K.wo[j] = pack2(r0[48 + d], r1[48 + d]);
    }
    K.bi2 = pack2(bx[d]      + bh[d]      + b_gates[d],      0.0f);
    K.bf2 = pack2(bx[16 + d] + bh[16 + d] + b_gates[16 + d], 0.0f);
    K.bc2 = pack2(bx[32 + d] + bh[32 + d] + b_gates[32 + d], 0.0f);
    K.bo2 = pack2(bx[48 + d] + bh[48 + d] + b_gates[48 + d], 0.0f);
    K.wp0 = w_peep[d]; K.wp1 = w_peep[16 + d]; K.wp2 = w_peep[32 + d];
    K.wld = W_lin[d];  K.bl  = b_lin[0];

    const int ngroups = (N + GROUP - 1) / GROUP;
    const int stride  = (int)gridDim.x * WPB;               // groups per sweep
    const int g0      = (int)blockIdx.x * WPB + warp;
    if (g0 >= ngroups) return;

    const int nmax0 = (N >= GROUP) ? (N - GROUP) : 0;       // clamped load base
    uint32_t sbase = (uint32_t)__cvta_generic_to_shared(&ring[warp][0][0]);

    // ---- prologue: fill stages 0..2 ----
#pragma unroll
    for (int st = 0; st < 3; ++st) {
        int gg = g0 + st * stride;
        int n0 = (gg < ngroups) ? gg * GROUP : nmax0;
        if (n0 > nmax0) n0 = nmax0;
        issue_group(sbase + st * ST_BYTES, lane, n0, x, h, c);
        cp_commit();
    }

    int st = 0;
    for (int g = g0; g < ngroups; g += stride) {
        cp_wait2();
        __syncwarp();

        // ---- prefetch stage st+3 ----
        {
            int gg = g + 3 * stride;
            int n0 = (gg < ngroups) ? gg * GROUP : nmax0;
            if (n0 > nmax0) n0 = nmax0;
            issue_group(sbase + ((st + 3) & 3) * ST_BYTES, lane, n0, x, h, c);
            cp_commit();
        }

        const float* S = &ring[warp][st][0];
        const int nb = g * GROUP;

        // ---- consume: 4 pairs (8 nodes) ----
#pragma unroll
        for (int q = 0; q < 4; ++q) {
            const int node = 2 * q + s;
            const ulonglong2* xv = reinterpret_cast<const ulonglong2*>(S + ST_X + node * 8);
            const ulonglong2* hv = reinterpret_cast<const ulonglong2*>(S + ST_H + node * 16);
            ulonglong2 xa = xv[0], xb = xv[1];
            ulonglong2 h0 = hv[0], h1 = hv[1], h2 = hv[2], h3 = hv[3];
            const float cv = S[ST_C + node * 16 + d];

            u64 ai = ffma2(xa.x, K.wi[0], K.bi2);
            u64 af = ffma2(xa.x, K.wf[0], K.bf2);
            u64 ac = ffma2(xa.x, K.wc[0], K.bc2);
            u64 ao = ffma2(xa.x, K.wo[0], K.bo2);
            u64 in1 = xa.y, in2 = xb.x, in3 = xb.y;
            u64 in4 = h0.x, in5 = h0.y, in6 = h1.x, in7 = h1.y;
            u64 in8 = h2.x, in9 = h2.y, in10 = h3.x, in11 = h3.y;
#define STEP(v, j) \
            ai = ffma2(v, K.wi[j], ai); af = ffma2(v, K.wf[j], af); \
            ac = ffma2(v, K.wc[j], ac); ao = ffma2(v, K.wo[j], ao);
            STEP(in1, 1)  STEP(in2, 2)  STEP(in3, 3)
            STEP(in4, 4)  STEP(in5, 5)  STEP(in6, 6)  STEP(in7, 7)
            STEP(in8, 8)  STEP(in9, 9)  STEP(in10, 10) STEP(in11, 11)
#undef STEP
            float g0f, g1f, gi, gf, gc, go;
            unpack2(ai, g0f, g1f); gi = g0f + g1f;
            unpack2(af, g0f, g1f); gf = g0f + g1f;
            unpack2(ac, g0f, g1f); gc = g0f + g1f;
            unpack2(ao, g0f, g1f); go = g0f + g1f;

            const float iv = sigmoid_f(fmaf(K.wp0, cv, gi));
            const float fv = sigmoid_f(fmaf(K.wp1, cv, gf));
            const float tv = tanh_f(gc);
            const float cn = fmaf(fv, cv, iv * tv);
            const float ov = sigmoid_f(fmaf(K.wp2, cn, go));
            const float hn = ov * tanh_f(cn);

            float r = fmaxf(hn, 0.0f) * K.wld;
            r += __shfl_xor_sync(0xffffffffu, r, 1);
            r += __shfl_xor_sync(0xffffffffu, r, 2);
            r += __shfl_xor_sync(0xffffffffu, r, 4);
            r += __shfl_xor_sync(0xffffffffu, r, 8);

            const int n = nb + node;
            if (n < N) {
                c_new[n * 16 + d] = cn;           // 128B coalesced per warp
                h_new[n * 16 + d] = hn;
                if (d == 0) out[n] = r + K.bl;
            }
        }

        __syncwarp();          // stage st free for the prefetch 3 iterations out
        st = (st + 1) & 3;
    }
    cp_wait0();
}

extern "C" void kernel_launch(void* const* d_in, const int* in_sizes, int n_in,
                              void* d_out, int out_size) {
    // metadata order: x, edge_index(unused), edge_attr(unused), h, c,
    //                 Wx, bx, Wh, bh, w_peep, b_gates, W_lin, b_lin
    const float* x  = (const float*)d_in[0];
    const float* h  = (const float*)d_in[3];
    const float* c  = (const float*)d_in[4];
    const float* Wx = (const float*)d_in[5];
    const float* bx = (const float*)d_in[6];
    const float* Wh = (const float*)d_in[7];
    const float* bh = (const float*)d_in[8];
    const float* wp = (const float*)d_in[9];
    const float* bg = (const float*)d_in[10];
    const float* wl = (const float*)d_in[11];
    const float* bl = (const float*)d_in[12];

    const int N = in_sizes[0] / 8;   // x is (N, 8)

    float* out = (float*)d_out;
    float* hn  = out + (size_t)N;
    float* cn  = hn + (size_t)N * 16;

    const int threads = 128;
    const int blocks  = 444;   // 3 resident blocks x 148 SMs, persistent
    gconvlstm_kernel<<<blocks, threads>>>(x, h, c, Wx, bx, Wh, bh, wp, bg, wl, bl,
                                          out, hn, cn, N);
}